// round 16
// baseline (speedup 1.0000x reference)
#include <cuda_runtime.h>
#include <cuda_bf16.h>
#include <cuda_fp16.h>
#include <cstdint>
#include <cstddef>

// ---------------------------------------------------------------------------
// MultiModalClassifier, GB300, mma.sync fp16 GEMMs, fp16 intermediates.
//   B=8192, D=1024, H=4 (hd=256), C=4, M=32768
// Algebra:
//   self_out = X@Weff^T + bS,  Weff = Wo_s@Wv_s, bS = Wo_s@bv_s + bo_s
//   cross: K_ij = Kc_i - Kc_j + bk_c, V_ij = Vc_i - Vc_j + bv_c
//   d = S + ctx@Wo_c^T + bo_c;  logits fused into GEMM2 epilogue.
// R16: ncu showed tensor=66.6% @ occ 12.2% -> retile 128x128/BK64/occ-2
// (8 warps, warp tile 64x32, 3 stages, single-buffered frags, <=128 regs).
// ---------------------------------------------------------------------------

#define NB 8192
#define DD 1024
#define MTOT 32768
#define HD 256
#define N1A 4096          // Q | Kc | Vc | S

// ------------------------------ scratch ------------------------------------
__device__ __half g_Xh   [(size_t)MTOT * DD];    // 64 MB
__device__ __half g_Wh   [(size_t)5120 * DD];    // 10 MB (Wq;Wkc;Wvc;Weff;Woc)
__device__ __half g_C1h  [(size_t)MTOT * N1A];   // 256 MB (Q|Kc|Vc|S)
__device__ __half g_A2h  [(size_t)MTOT * DD];    // 64 MB  (ctx fp16)
__device__ __half g_Wos16[(size_t)DD * DD];      // 2 MB  (Wo_s fp16)
__device__ __half g_WvsT16[(size_t)DD * DD];     // 2 MB  (Wv_s^T fp16)
__device__ float  g_plog [(size_t)8 * MTOT * 4]; // 4 MB logits partials
__device__ float  g_b1a[N1A];
__device__ float  g_zero[DD];                     // never written: zeros

// --------------------------- PTX helpers -----------------------------------
__device__ __forceinline__ uint32_t smem_u32(const void* p) {
    uint32_t a;
    asm("{ .reg .u64 t; cvta.to.shared.u64 t, %1; cvt.u32.u64 %0, t; }"
        : "=r"(a) : "l"(p));
    return a;
}

#define CP_ASYNC16(dst, src) \
    asm volatile("cp.async.cg.shared.global [%0], [%1], 16;" :: "r"(dst), "l"(src))
#define CP_COMMIT() asm volatile("cp.async.commit_group;" ::: "memory")
#define CP_WAIT(n)  asm volatile("cp.async.wait_group %0;" :: "n"(n) : "memory")

#define LDMATRIX_X4(r0, r1, r2, r3, addr)                                     \
    asm volatile("ldmatrix.sync.aligned.m8n8.x4.shared.b16 {%0,%1,%2,%3}, [%4];" \
                 : "=r"(r0), "=r"(r1), "=r"(r2), "=r"(r3) : "r"(addr))

#define MMA_F16(d0, d1, d2, d3, a0, a1, a2, a3, b0, b1)                       \
    asm volatile("mma.sync.aligned.m16n8k16.row.col.f32.f16.f16.f32 "         \
                 "{%0,%1,%2,%3}, {%4,%5,%6,%7}, {%8,%9}, {%0,%1,%2,%3};"      \
                 : "+f"(d0), "+f"(d1), "+f"(d2), "+f"(d3)                     \
                 : "r"(a0), "r"(a1), "r"(a2), "r"(a3), "r"(b0), "r"(b1))

// --------------------------- GEMM body -------------------------------------
// C tile = A[brow.., ld] @ B[bcol.., ld]^T + bias (+ fp16 add).
// CTA tile 128x128, BK=64, SW128 swizzle, 3-stage cp.async, occupancy 2,
// 8 warps (2x4), warp tile 64x32, single-buffered fragments.
// DOLOG: also emit per-CTA logits partials (deterministic).
#define STAGES 3
#define STAGE_BYTES 32768          // A 16KB + B 16KB
#define GEMM_SMEM (STAGES * STAGE_BYTES)

__device__ __forceinline__ void load_stage(
    const uint16_t* __restrict__ A, const uint16_t* __restrict__ B,
    int ld, int brow, int bcol, int kb, uint32_t st, int tid)
{
    #pragma unroll
    for (int i = 0; i < 8; i++) {
        int id = tid + 256 * i;
        if (id < 1024) {                       // A: 128 rows x 8 chunks
            int row = id >> 3, c = id & 7;
            const uint16_t* g = A + (size_t)(brow + row) * ld + kb * 64 + c * 8;
            CP_ASYNC16(st + row * 128 + ((c ^ (row & 7)) * 16), g);
        } else {                               // B: 128 rows x 8 chunks
            int idb = id - 1024;
            int row = idb >> 3, c = idb & 7;
            const uint16_t* g = B + (size_t)(bcol + row) * ld + kb * 64 + c * 8;
            CP_ASYNC16(st + 16384 + row * 128 + ((c ^ (row & 7)) * 16), g);
        }
    }
}

template <bool OUT16, bool DOLOG>
__device__ __forceinline__ void gemm_body(
    const uint16_t* __restrict__ A, const uint16_t* __restrict__ B,
    const float* __restrict__ bias,
    const __half* __restrict__ add, int add_ld,
    void* __restrict__ Cv, int N, int K, int ld,
    int brow, int bcol, int bxid,
    const float* __restrict__ Wc, float* __restrict__ plog, char* smem)
{
    __shared__ float sred[4][128][4];            // used only when DOLOG
    const uint32_t sbase = smem_u32(smem);
    const int tid  = threadIdx.x;
    const int wid  = tid >> 5, lane = tid & 31;
    const int wm   = wid >> 2, wn = wid & 3;     // 2 x 4 warps
    const int NKB  = K >> 6;

    float acc[4][4][4];
    #pragma unroll
    for (int i = 0; i < 4; i++)
        #pragma unroll
        for (int j = 0; j < 4; j++)
            #pragma unroll
            for (int k = 0; k < 4; k++) acc[i][j][k] = 0.f;

    load_stage(A, B, ld, brow, bcol, 0, sbase, tid);               CP_COMMIT();
    load_stage(A, B, ld, brow, bcol, 1, sbase + STAGE_BYTES, tid); CP_COMMIT();

    int a_off[4], a_sw[4];
    #pragma unroll
    for (int mt = 0; mt < 4; mt++) {
        int r = wm * 64 + mt * 16 + (lane & 15);
        a_off[mt] = r * 128; a_sw[mt] = r & 7;
    }
    const int a_kh = lane >> 4;
    int b_off[2], b_sw[2];
    #pragma unroll
    for (int np = 0; np < 2; np++) {
        int r = wn * 32 + np * 16 + ((lane >> 4) & 1) * 8 + (lane & 7);
        b_off[np] = r * 128; b_sw[np] = r & 7;
    }
    const int b_kh = (lane >> 3) & 1;

    for (int kb = 0; kb < NKB; kb++) {
        if (kb < NKB - 1) CP_WAIT(1);
        else              CP_WAIT(0);
        __syncthreads();
        if (kb + 2 < NKB) {
            load_stage(A, B, ld, brow, bcol, kb + 2,
                       sbase + ((kb + 2) % 3) * STAGE_BYTES, tid);
            CP_COMMIT();
        }
        const uint32_t sA = sbase + (kb % 3) * STAGE_BYTES;
        const uint32_t sB = sA + 16384;

        #pragma unroll
        for (int ks = 0; ks < 4; ks++) {
            uint32_t af[4][4], bf[2][4];
            const int cca = ks * 2 + a_kh, ccb = ks * 2 + b_kh;
            #pragma unroll
            for (int mt = 0; mt < 4; mt++)
                LDMATRIX_X4(af[mt][0], af[mt][1], af[mt][2], af[mt][3],
                            sA + a_off[mt] + ((cca ^ a_sw[mt]) * 16));
            #pragma unroll
            for (int np = 0; np < 2; np++)
                LDMATRIX_X4(bf[np][0], bf[np][1], bf[np][2], bf[np][3],
                            sB + b_off[np] + ((ccb ^ b_sw[np]) * 16));
            #pragma unroll
            for (int mt = 0; mt < 4; mt++)
                #pragma unroll
                for (int nt = 0; nt < 4; nt++)
                    MMA_F16(acc[mt][nt][0], acc[mt][nt][1],
                            acc[mt][nt][2], acc[mt][nt][3],
                            af[mt][0], af[mt][1], af[mt][2], af[mt][3],
                            bf[nt >> 1][(nt & 1) * 2],
                            bf[nt >> 1][(nt & 1) * 2 + 1]);
        }
    }

    #pragma unroll
    for (int mt = 0; mt < 4; mt++) {
        const int r0 = brow + wm * 64 + mt * 16 + (lane >> 2);
        float p0[4] = {0.f, 0.f, 0.f, 0.f}, p1[4] = {0.f, 0.f, 0.f, 0.f};
        #pragma unroll
        for (int nt = 0; nt < 4; nt++) {
            const int c0 = bcol + wn * 32 + nt * 8 + (lane & 3) * 2;
            const float bx = bias[c0], by = bias[c0 + 1];
            float a0 = acc[mt][nt][0] + bx, a1 = acc[mt][nt][1] + by;
            float a2 = acc[mt][nt][2] + bx, a3 = acc[mt][nt][3] + by;
            if (add) {
                a0 += __half2float(add[(size_t)r0 * add_ld + c0]);
                a1 += __half2float(add[(size_t)r0 * add_ld + c0 + 1]);
                a2 += __half2float(add[(size_t)(r0 + 8) * add_ld + c0]);
                a3 += __half2float(add[(size_t)(r0 + 8) * add_ld + c0 + 1]);
            }
            if (OUT16) {
                __half* C = (__half*)Cv;
                __half2 v0 = __floats2half2_rn(a0, a1);
                __half2 v1 = __floats2half2_rn(a2, a3);
                *(__half2*)&C[(size_t)r0 * N + c0]       = v0;
                *(__half2*)&C[(size_t)(r0 + 8) * N + c0] = v1;
            } else {
                float* C = (float*)Cv;
                float2 v0 = { a0, a1 }, v1 = { a2, a3 };
                *(float2*)&C[(size_t)r0 * N + c0]       = v0;
                *(float2*)&C[(size_t)(r0 + 8) * N + c0] = v1;
            }
            if (DOLOG) {
                #pragma unroll
                for (int c = 0; c < 4; c++) {
                    float w0 = Wc[c * DD + c0], w1 = Wc[c * DD + c0 + 1];
                    p0[c] = fmaf(a0, w0, fmaf(a1, w1, p0[c]));
                    p1[c] = fmaf(a2, w0, fmaf(a3, w1, p1[c]));
                }
            }
        }
        if (DOLOG) {
            #pragma unroll
            for (int c = 0; c < 4; c++) {
                p0[c] += __shfl_xor_sync(0xffffffffu, p0[c], 1);
                p0[c] += __shfl_xor_sync(0xffffffffu, p0[c], 2);
                p1[c] += __shfl_xor_sync(0xffffffffu, p1[c], 1);
                p1[c] += __shfl_xor_sync(0xffffffffu, p1[c], 2);
            }
            if ((lane & 3) == 0) {
                int rl = wm * 64 + mt * 16 + (lane >> 2);
                #pragma unroll
                for (int c = 0; c < 4; c++) {
                    sred[wn][rl][c]     = p0[c];
                    sred[wn][rl + 8][c] = p1[c];
                }
            }
        }
    }
    if (DOLOG) {
        __syncthreads();
        for (int t = tid; t < 512; t += 256) {
            int row = t >> 2, c = t & 3;
            float s = sred[0][row][c] + sred[1][row][c]
                    + sred[2][row][c] + sred[3][row][c];
            plog[((size_t)bxid * MTOT + brow + row) * 4 + c] = s;
        }
    }
}

// GEMM1: fp16 in/out, ld == K.
__global__ __launch_bounds__(256, 2)
void gemm1_kernel(const uint16_t* __restrict__ A, const uint16_t* __restrict__ B,
                  const float* __restrict__ bias, __half* __restrict__ C,
                  int N, int K)
{
    extern __shared__ __align__(1024) char smem[];
    gemm_body<true, false>(A, B, bias, nullptr, 0, C, N, K, K,
                           blockIdx.y * 128, blockIdx.x * 128, 0,
                           nullptr, nullptr, smem);
}

// GEMM2: fp16 in, fp32 out, fp16 addend (S), fused logits partials.
__global__ __launch_bounds__(256, 2)
void gemm2_kernel(const uint16_t* __restrict__ A, const uint16_t* __restrict__ B,
                  const float* __restrict__ bias,
                  const __half* __restrict__ add, int add_ld,
                  float* __restrict__ C, int N, int K,
                  const float* __restrict__ Wc, float* __restrict__ plog)
{
    extern __shared__ __align__(1024) char smem[];
    gemm_body<false, true>(A, B, bias, add, add_ld, C, N, K, K,
                           blockIdx.y * 128, blockIdx.x * 128,
                           blockIdx.x, Wc, plog, smem);
}

// Reduce logits partials (fixed order over 8 column blocks) + bc.
__global__ __launch_bounds__(256) void reduce_logits_kernel(
    const float* __restrict__ plog, const float* __restrict__ bc,
    float* __restrict__ logits)
{
    size_t idx = (size_t)blockIdx.x * 256 + threadIdx.x;   // MTOT*4 total
    float s = bc[idx & 3];
    #pragma unroll
    for (int c = 0; c < 8; c++)
        s += plog[(size_t)c * MTOT * 4 + idx];
    logits[idx] = s;
}

// --------------------------- cast kernel -----------------------------------
// Blocks [0, MTOT): stacked X -> Xh.
// Blocks [MTOT, MTOT+5120): straight casts Wq->0, Wkc->1024, Wvc->2048,
//   Woc->4096 (rows of Wh), Wo_s -> Wos16.
// Blocks [MTOT+5120, MTOT+6144): tiled transpose-cast Wv_s -> WvsT16.
__global__ __launch_bounds__(256) void cast_all_kernel(
    const float* __restrict__ X1, const float* __restrict__ X2,
    const float* __restrict__ X3, const float* __restrict__ X4,
    const float* __restrict__ Wq, const float* __restrict__ Wkc,
    const float* __restrict__ Wvc, const float* __restrict__ Woc,
    const float* __restrict__ Wos, const float* __restrict__ Wvs,
    __half* __restrict__ Xh, __half* __restrict__ Wh,
    __half* __restrict__ Wos16, __half* __restrict__ WvsT16)
{
    if (blockIdx.x < MTOT) {
        size_t idx = (size_t)blockIdx.x * 256 + threadIdx.x;
        size_t r = idx >> 8;
        int c4 = (int)(idx & 255) * 4;
        const float* src = (r < NB) ? X1 : (r < 2 * NB) ? X2
                         : (r < 3 * NB) ? X3 : X4;
        float4 v = *(const float4*)&src[(r & (NB - 1)) * DD + c4];
        __half hf[4] = { __float2half(v.x), __float2half(v.y),
                         __float2half(v.z), __float2half(v.w) };
        *(uint2*)&Xh[r * DD + c4] = *(uint2*)hf;
    } else if (blockIdx.x < MTOT + 5120) {
        size_t idx = (size_t)(blockIdx.x - MTOT) * 256 + threadIdx.x;
        int sel = (int)(idx >> 18);             // 2^18 float4 per matrix
        size_t off = (idx & ((1u << 18) - 1)) * 4;
        const float* src = (sel == 0) ? Wq : (sel == 1) ? Wkc
                         : (sel == 2) ? Wvc : (sel == 3) ? Woc : Wos;
        __half* dst = (sel == 4) ? Wos16
                    : Wh + (size_t)((sel == 3) ? 4096 : sel * 1024) * DD;
        float4 v = *(const float4*)&src[off];
        __half h[4] = { __float2half(v.x), __float2half(v.y),
                        __float2half(v.z), __float2half(v.w) };
        *(uint2*)&dst[off] = *(uint2*)h;
    } else {
        __shared__ float tile[32][33];
        const int bb = blockIdx.x - (MTOT + 5120);
        const int i0 = (bb & 31) * 32;         // i tile (cols of Wvs)
        const int m0 = (bb >> 5) * 32;         // m tile (rows of Wvs)
        const int tx = threadIdx.x & 31, ty = threadIdx.x >> 5;   // 32 x 8
        #pragma unroll
        for (int r = 0; r < 4; r++)
            tile[ty * 4 + r][tx] = Wvs[(size_t)(m0 + ty * 4 + r) * DD + i0 + tx];
        __syncthreads();
        const int il = threadIdx.x >> 3;       // 0..31
        const int mq = (threadIdx.x & 7) * 4;  // 0,4,..,28
        __half h[4];
        #pragma unroll
        for (int r = 0; r < 4; r++)
            h[r] = __float2half(tile[mq + r][il]);
        *(uint2*)&WvsT16[(size_t)(i0 + il) * DD + m0 + mq] = *(uint2*)h;
    }
}

// --------------------------- bias kernel -----------------------------------
__device__ __forceinline__ float wsum(float v) {
    #pragma unroll
    for (int o = 16; o; o >>= 1) v += __shfl_xor_sync(0xffffffffu, v, o);
    return v;
}

// Merged: b1a[0..1023]=bq, [1024..3071]=0, [3072+o]=Wos[o,:]@bvs + bos[o].
__global__ __launch_bounds__(256) void bias_all_kernel(
    const float* __restrict__ bq,
    const float* __restrict__ Wos, const float* __restrict__ bvs,
    const float* __restrict__ bos, float* __restrict__ b1a)
{
    int idx = blockIdx.x * 256 + threadIdx.x;   // 128 blocks -> 32768 threads
    if (idx < DD)           b1a[idx] = bq[idx];
    else if (idx < 3 * DD)  b1a[idx] = 0.f;

    int o = blockIdx.x * 8 + (threadIdx.x >> 5);
    int lane = threadIdx.x & 31;
    float s = 0.f;
    for (int k = lane; k < DD; k += 32)
        s = fmaf(Wos[(size_t)o * DD + k], bvs[k], s);
    s = wsum(s);
    if (lane == 0) b1a[3 * DD + o] = s + bos[o];
}

// --------------------------- combine ---------------------------------------
// ctx_i = Vc_i + bv_c - sum_j a_ij Vc_j, fp16 in (C1h) / fp16 out (A2h).
__global__ __launch_bounds__(128) void combine_kernel(
    const __half* __restrict__ C1h,   // Q | Kc | Vc | S  (ld 4096)
    const float* __restrict__ bk, const float* __restrict__ bv,
    __half* __restrict__ A2h)
{
    const int b    = blockIdx.x;
    const int h    = threadIdx.x >> 5;
    const int lane = threadIdx.x & 31;
    const int base_d = h * HD + lane;

    float q[4][8], kc[4][8], vc[4][8];
    #pragma unroll
    for (int i = 0; i < 4; i++) {
        size_t row = (size_t)(i * NB + b) * N1A + base_d;
        #pragma unroll
        for (int e = 0; e < 8; e++) {
            q [i][e] = __half2float(C1h[row + e * 32]);
            kc[i][e] = __half2float(C1h[row + 1024 + e * 32]);
            vc[i][e] = __half2float(C1h[row + 2048 + e * 32]);
        }
    }
    float bke[8], bve[8];
    #pragma unroll
    for (int e = 0; e < 8; e++) {
        bke[e] = bk[base_d + e * 32];
        bve[e] = bv[base_d + e * 32];
    }

    float a[4][4];
    #pragma unroll
    for (int i = 0; i < 4; i++) {
        float s[4];
        #pragma unroll
        for (int j = 0; j < 4; j++) {
            float p = 0.f;
            #pragma unroll
            for (int e = 0; e < 8; e++)
                p = fmaf(q[i][e], kc[i][e] - kc[j][e] + bke[e], p);
            s[j] = wsum(p) * (1.f / 16.f);
        }
        float m = -1e30f;
        #pragma unroll
        for (int j = 0; j < 4; j++) if (j != i && s[j] > m) m = s[j];
        float den = 0.f;
        #pragma unroll
        for (int j = 0; j < 4; j++) {
            float ex = (j == i) ? 0.f : __expf(s[j] - m);
            a[i][j] = ex; den += ex;
        }
        float inv = 1.f / den;
        #pragma unroll
        for (int j = 0; j < 4; j++) a[i][j] *= inv;
    }

    #pragma unroll
    for (int i = 0; i < 4; i++) {
        __half* row = A2h + (size_t)(i * NB + b) * DD;
        #pragma unroll
        for (int e = 0; e < 8; e++) {
            float c = vc[i][e] + bve[e];
            #pragma unroll
            for (int j = 0; j < 4; j++)
                c = fmaf(-a[i][j], vc[j][e], c);
            row[base_d + e * 32] = __float2half(c);
        }
    }
}

// ---------------------------------------------------------------------------
extern "C" void kernel_launch(void* const* d_in, const int* in_sizes, int n_in,
                              void* d_out, int out_size)
{
    const float* X1   = (const float*)d_in[0];
    const float* X2   = (const float*)d_in[1];
    const float* X3   = (const float*)d_in[2];
    const float* X4   = (const float*)d_in[3];
    const float* Wq   = (const float*)d_in[4];
    const float* bq   = (const float*)d_in[5];
    const float* Wv_s = (const float*)d_in[8];
    const float* bv_s = (const float*)d_in[9];
    const float* Wo_s = (const float*)d_in[10];
    const float* bo_s = (const float*)d_in[11];
    const float* Wk_c = (const float*)d_in[12];
    const float* bk_c = (const float*)d_in[13];
    const float* Wv_c = (const float*)d_in[14];
    const float* bv_c = (const float*)d_in[15];
    const float* Wo_c = (const float*)d_in[16];
    const float* bo_c = (const float*)d_in[17];
    const float* Wc   = (const float*)d_in[18];
    const float* bc   = (const float*)d_in[19];

    float* out    = (float*)d_out;
    float* logits = out + (size_t)MTOT * DD;

    __half *gXh, *gWh, *gC1h, *gA2h, *gWos16, *gWvsT16;
    float *gPlog, *gb1a, *gzero;
    cudaGetSymbolAddress((void**)&gXh,     g_Xh);
    cudaGetSymbolAddress((void**)&gWh,     g_Wh);
    cudaGetSymbolAddress((void**)&gC1h,    g_C1h);
    cudaGetSymbolAddress((void**)&gA2h,    g_A2h);
    cudaGetSymbolAddress((void**)&gWos16,  g_Wos16);
    cudaGetSymbolAddress((void**)&gWvsT16, g_WvsT16);
    cudaGetSymbolAddress((void**)&gPlog,   g_plog);
    cudaGetSymbolAddress((void**)&gb1a,    g_b1a);
    cudaGetSymbolAddress((void**)&gzero,   g_zero);

    cudaFuncSetAttribute((const void*)gemm1_kernel,
                         cudaFuncAttributeMaxDynamicSharedMemorySize, GEMM_SMEM);
    cudaFuncSetAttribute((const void*)gemm2_kernel,
                         cudaFuncAttributeMaxDynamicSharedMemorySize, GEMM_SMEM);

    // prep: all fp16 casts (X, 5 weight matrices, Wv_s^T) in one launch
    cast_all_kernel<<<MTOT + 6144, 256>>>(
        X1, X2, X3, X4, Wq, Wk_c, Wv_c, Wo_c, Wo_s, Wv_s,
        gXh, gWh, gWos16, gWvsT16);

    // Weff = Wo_s@Wv_s (fp16 in, fp32 accum, fp16 out straight into Wh S block)
    gemm1_kernel<<<dim3(8, 8), 256, GEMM_SMEM>>>(
        (const uint16_t*)gWos16, (const uint16_t*)gWvsT16, gzero,
        gWh + (size_t)3072 * DD, DD, DD);

    bias_all_kernel<<<128, 256>>>(bq, Wo_s, bv_s, bo_s, gb1a);

    // GEMM1 (fp16 in/out): C1h[32768,4096] = Xh @ [Wq;Wkc;Wvc;Weff]^T + b1a
    gemm1_kernel<<<dim3(N1A / 128, MTOT / 128), 256, GEMM_SMEM>>>(
        (const uint16_t*)gXh, (const uint16_t*)gWh, gb1a, gC1h, N1A, DD);

    // attention combine -> ctx fp16 into A2h
    combine_kernel<<<NB, 128>>>(gC1h, bk_c, bv_c, gA2h);

    // GEMM2 (fp16 in, fp32 out): d = ctx @ Wo_c^T + bo_c + S, with fused
    // per-column-block logits partials (deterministic).
    gemm2_kernel<<<dim3(DD / 128, MTOT / 128), 256, GEMM_SMEM>>>(
        (const uint16_t*)gA2h, (const uint16_t*)(gWh + (size_t)4096 * DD),
        bo_c, gC1h + 3072, N1A, out, DD, DD, Wc, gPlog);

    // logits = sum of 8 column-block partials (fixed order) + bc
    reduce_logits_kernel<<<MTOT * 4 / 256, 256>>>(gPlog, bc, logits);
}

// round 17
// speedup vs baseline: 1.0161x; 1.0161x over previous
#include <cuda_runtime.h>
#include <cuda_bf16.h>
#include <cuda_fp16.h>
#include <cstdint>
#include <cstddef>

// ---------------------------------------------------------------------------
// MultiModalClassifier, GB300, mma.sync fp16 GEMMs, fp16 intermediates.
//   B=8192, D=1024, H=4 (hd=256), C=4, M=32768
// Algebra:
//   self_out = X@Weff^T + bS,  Weff = Wo_s@Wv_s, bS = Wo_s@bv_s + bo_s
//   cross: K_ij = Kc_i - Kc_j + bk_c, V_ij = Vc_i - Vc_j + bv_c
//   d = S + ctx@Wo_c^T + bo_c;  logits fused into GEMM2 epilogue.
// R17: barrier per 2 k-blocks (CP_WAIT(0) -> barrier -> issue 2 loads ->
// compute 2 kbs) to break per-kb warp phase-lock; tiles back to 128x256/occ-1.
// ---------------------------------------------------------------------------

#define NB 8192
#define DD 1024
#define MTOT 32768
#define HD 256
#define N1A 4096          // Q | Kc | Vc | S

// ------------------------------ scratch ------------------------------------
__device__ __half g_Xh   [(size_t)MTOT * DD];    // 64 MB
__device__ __half g_Wh   [(size_t)5120 * DD];    // 10 MB (Wq;Wkc;Wvc;Weff;Woc)
__device__ __half g_C1h  [(size_t)MTOT * N1A];   // 256 MB (Q|Kc|Vc|S)
__device__ __half g_A2h  [(size_t)MTOT * DD];    // 64 MB  (ctx fp16)
__device__ __half g_Wos16[(size_t)DD * DD];      // 2 MB  (Wo_s fp16)
__device__ __half g_WvsT16[(size_t)DD * DD];     // 2 MB  (Wv_s^T fp16)
__device__ float  g_plog [(size_t)4 * MTOT * 4]; // 2 MB logits partials
__device__ float  g_b1a[N1A];
__device__ float  g_zero[DD];                     // never written: zeros

// --------------------------- PTX helpers -----------------------------------
__device__ __forceinline__ uint32_t smem_u32(const void* p) {
    uint32_t a;
    asm("{ .reg .u64 t; cvta.to.shared.u64 t, %1; cvt.u32.u64 %0, t; }"
        : "=r"(a) : "l"(p));
    return a;
}

#define CP_ASYNC16(dst, src) \
    asm volatile("cp.async.cg.shared.global [%0], [%1], 16;" :: "r"(dst), "l"(src))
#define CP_COMMIT() asm volatile("cp.async.commit_group;" ::: "memory")
#define CP_WAIT(n)  asm volatile("cp.async.wait_group %0;" :: "n"(n) : "memory")

#define LDMATRIX_X4(r0, r1, r2, r3, addr)                                     \
    asm volatile("ldmatrix.sync.aligned.m8n8.x4.shared.b16 {%0,%1,%2,%3}, [%4];" \
                 : "=r"(r0), "=r"(r1), "=r"(r2), "=r"(r3) : "r"(addr))

#define MMA_F16(d0, d1, d2, d3, a0, a1, a2, a3, b0, b1)                       \
    asm volatile("mma.sync.aligned.m16n8k16.row.col.f32.f16.f16.f32 "         \
                 "{%0,%1,%2,%3}, {%4,%5,%6,%7}, {%8,%9}, {%0,%1,%2,%3};"      \
                 : "+f"(d0), "+f"(d1), "+f"(d2), "+f"(d3)                     \
                 : "r"(a0), "r"(a1), "r"(a2), "r"(a3), "r"(b0), "r"(b1))

// --------------------------- GEMM body -------------------------------------
// C tile = A[brow.., ld] @ B[bcol.., ld]^T + bias (+ fp16 add).
// CTA tile 128x256, BK=64, SW128 swizzle, 4-stage cp.async, 8 warps (2x4),
// warp tile 64x64, double-buffered fragments, ONE barrier per 2 k-blocks.
// DOLOG: also emit per-CTA logits partials (deterministic).
#define STAGES 4
#define STAGE_BYTES 49152          // A 16KB + B 32KB
#define GEMM_SMEM (STAGES * STAGE_BYTES)

__device__ __forceinline__ void load_stage(
    const uint16_t* __restrict__ A, const uint16_t* __restrict__ B,
    int ld, int brow, int bcol, int kb, uint32_t st, int tid)
{
    #pragma unroll
    for (int i = 0; i < 12; i++) {
        int id = tid + 256 * i;
        if (id < 1024) {                       // A: 128 rows x 8 chunks
            int row = id >> 3, c = id & 7;
            const uint16_t* g = A + (size_t)(brow + row) * ld + kb * 64 + c * 8;
            CP_ASYNC16(st + row * 128 + ((c ^ (row & 7)) * 16), g);
        } else {                               // B: 256 rows x 8 chunks
            int idb = id - 1024;
            int row = idb >> 3, c = idb & 7;
            const uint16_t* g = B + (size_t)(bcol + row) * ld + kb * 64 + c * 8;
            CP_ASYNC16(st + 16384 + row * 128 + ((c ^ (row & 7)) * 16), g);
        }
    }
}

template <bool OUT16, bool DOLOG>
__device__ __forceinline__ void gemm_body(
    const uint16_t* __restrict__ A, const uint16_t* __restrict__ B,
    const float* __restrict__ bias,
    const __half* __restrict__ add, int add_ld,
    void* __restrict__ Cv, int N, int K, int ld,
    int brow, int bcol, int bxid,
    const float* __restrict__ Wc, float* __restrict__ plog, char* smem)
{
    __shared__ float sred[4][128][4];            // used only when DOLOG
    const uint32_t sbase = smem_u32(smem);
    const int tid  = threadIdx.x;
    const int wid  = tid >> 5, lane = tid & 31;
    const int wm   = wid >> 2, wn = wid & 3;     // 2 x 4 warps
    const int NKB  = K >> 6;                     // even for all uses

    float acc[4][8][4];
    #pragma unroll
    for (int i = 0; i < 4; i++)
        #pragma unroll
        for (int j = 0; j < 8; j++)
            #pragma unroll
            for (int k = 0; k < 4; k++) acc[i][j][k] = 0.f;

    load_stage(A, B, ld, brow, bcol, 0, sbase, tid);               CP_COMMIT();
    load_stage(A, B, ld, brow, bcol, 1, sbase + STAGE_BYTES, tid); CP_COMMIT();

    int a_off[4], a_sw[4];
    #pragma unroll
    for (int mt = 0; mt < 4; mt++) {
        int r = wm * 64 + mt * 16 + (lane & 15);
        a_off[mt] = r * 128; a_sw[mt] = r & 7;
    }
    const int a_kh = lane >> 4;
    int b_off[4], b_sw[4];
    #pragma unroll
    for (int np = 0; np < 4; np++) {
        int r = wn * 64 + np * 16 + ((lane >> 4) & 1) * 8 + (lane & 7);
        b_off[np] = r * 128; b_sw[np] = r & 7;
    }
    const int b_kh = (lane >> 3) & 1;

    uint32_t af[2][4][4], bf[2][4][4];           // double-buffered fragments

    #define LOAD_FRAGS(bi, ks, sA, sB)                                        \
        do {                                                                  \
            const int cca = (ks) * 2 + a_kh, ccb = (ks) * 2 + b_kh;           \
            _Pragma("unroll")                                                 \
            for (int mt = 0; mt < 4; mt++)                                    \
                LDMATRIX_X4(af[bi][mt][0], af[bi][mt][1],                     \
                            af[bi][mt][2], af[bi][mt][3],                     \
                            (sA) + a_off[mt] + ((cca ^ a_sw[mt]) * 16));      \
            _Pragma("unroll")                                                 \
            for (int np = 0; np < 4; np++)                                    \
                LDMATRIX_X4(bf[bi][np][0], bf[bi][np][1],                     \
                            bf[bi][np][2], bf[bi][np][3],                     \
                            (sB) + b_off[np] + ((ccb ^ b_sw[np]) * 16));      \
        } while (0)

    // Mainloop: 2 k-blocks per barrier.
    //   CP_WAIT(0): my groups for kb,kb+1 arrived (only 2 outstanding)
    //   barrier:    all threads' data visible AND all finished kb-2,kb-1
    //   then issue loads kb+2,kb+3 (their buffers are now free) + compute.
    for (int kb = 0; kb < NKB; kb += 2) {
        CP_WAIT(0);
        __syncthreads();
        if (kb + 2 < NKB) {
            load_stage(A, B, ld, brow, bcol, kb + 2,
                       sbase + ((kb + 2) & 3) * STAGE_BYTES, tid);
            CP_COMMIT();
            load_stage(A, B, ld, brow, bcol, kb + 3,
                       sbase + ((kb + 3) & 3) * STAGE_BYTES, tid);
            CP_COMMIT();
        }
        #pragma unroll
        for (int kk = 0; kk < 2; kk++) {
            const uint32_t sA = sbase + ((kb + kk) & 3) * STAGE_BYTES;
            const uint32_t sB = sA + 16384;
            LOAD_FRAGS(0, 0, sA, sB);
            #pragma unroll
            for (int ks = 0; ks < 4; ks++) {
                if (ks < 3) LOAD_FRAGS((ks + 1) & 1, ks + 1, sA, sB);
                const int cu = ks & 1;
                #pragma unroll
                for (int mt = 0; mt < 4; mt++)
                    #pragma unroll
                    for (int nt = 0; nt < 8; nt++)
                        MMA_F16(acc[mt][nt][0], acc[mt][nt][1],
                                acc[mt][nt][2], acc[mt][nt][3],
                                af[cu][mt][0], af[cu][mt][1],
                                af[cu][mt][2], af[cu][mt][3],
                                bf[cu][nt >> 1][(nt & 1) * 2],
                                bf[cu][nt >> 1][(nt & 1) * 2 + 1]);
            }
        }
    }
    #undef LOAD_FRAGS

    #pragma unroll
    for (int mt = 0; mt < 4; mt++) {
        const int r0 = brow + wm * 64 + mt * 16 + (lane >> 2);
        float p0[4] = {0.f, 0.f, 0.f, 0.f}, p1[4] = {0.f, 0.f, 0.f, 0.f};
        #pragma unroll
        for (int nt = 0; nt < 8; nt++) {
            const int c0 = bcol + wn * 64 + nt * 8 + (lane & 3) * 2;
            const float bx = bias[c0], by = bias[c0 + 1];
            float a0 = acc[mt][nt][0] + bx, a1 = acc[mt][nt][1] + by;
            float a2 = acc[mt][nt][2] + bx, a3 = acc[mt][nt][3] + by;
            if (add) {
                a0 += __half2float(add[(size_t)r0 * add_ld + c0]);
                a1 += __half2float(add[(size_t)r0 * add_ld + c0 + 1]);
                a2 += __half2float(add[(size_t)(r0 + 8) * add_ld + c0]);
                a3 += __half2float(add[(size_t)(r0 + 8) * add_ld + c0 + 1]);
            }
            if (OUT16) {
                __half* C = (__half*)Cv;
                __half2 v0 = __floats2half2_rn(a0, a1);
                __half2 v1 = __floats2half2_rn(a2, a3);
                *(__half2*)&C[(size_t)r0 * N + c0]       = v0;
                *(__half2*)&C[(size_t)(r0 + 8) * N + c0] = v1;
            } else {
                float* C = (float*)Cv;
                float2 v0 = { a0, a1 }, v1 = { a2, a3 };
                *(float2*)&C[(size_t)r0 * N + c0]       = v0;
                *(float2*)&C[(size_t)(r0 + 8) * N + c0] = v1;
            }
            if (DOLOG) {
                #pragma unroll
                for (int c = 0; c < 4; c++) {
                    float w0 = Wc[c * DD + c0], w1 = Wc[c * DD + c0 + 1];
                    p0[c] = fmaf(a0, w0, fmaf(a1, w1, p0[c]));
                    p1[c] = fmaf(a2, w0, fmaf(a3, w1, p1[c]));
                }
            }
        }
        if (DOLOG) {
            #pragma unroll
            for (int c = 0; c < 4; c++) {
                p0[c] += __shfl_xor_sync(0xffffffffu, p0[c], 1);
                p0[c] += __shfl_xor_sync(0xffffffffu, p0[c], 2);
                p1[c] += __shfl_xor_sync(0xffffffffu, p1[c], 1);
                p1[c] += __shfl_xor_sync(0xffffffffu, p1[c], 2);
            }
            if ((lane & 3) == 0) {
                int rl = wm * 64 + mt * 16 + (lane >> 2);
                #pragma unroll
                for (int c = 0; c < 4; c++) {
                    sred[wn][rl][c]     = p0[c];
                    sred[wn][rl + 8][c] = p1[c];
                }
            }
        }
    }
    if (DOLOG) {
        __syncthreads();
        for (int t = tid; t < 512; t += 256) {
            int row = t >> 2, c = t & 3;
            float s = sred[0][row][c] + sred[1][row][c]
                    + sred[2][row][c] + sred[3][row][c];
            plog[((size_t)bxid * MTOT + brow + row) * 4 + c] = s;
        }
    }
}

// GEMM1: fp16 in/out, ld == K.
__global__ __launch_bounds__(256, 1)
void gemm1_kernel(const uint16_t* __restrict__ A, const uint16_t* __restrict__ B,
                  const float* __restrict__ bias, __half* __restrict__ C,
                  int N, int K)
{
    extern __shared__ __align__(1024) char smem[];
    gemm_body<true, false>(A, B, bias, nullptr, 0, C, N, K, K,
                           blockIdx.y * 128, blockIdx.x * 256, 0,
                           nullptr, nullptr, smem);
}

// GEMM2: fp16 in, fp32 out, fp16 addend (S), fused logits partials.
__global__ __launch_bounds__(256, 1)
void gemm2_kernel(const uint16_t* __restrict__ A, const uint16_t* __restrict__ B,
                  const float* __restrict__ bias,
                  const __half* __restrict__ add, int add_ld,
                  float* __restrict__ C, int N, int K,
                  const float* __restrict__ Wc, float* __restrict__ plog)
{
    extern __shared__ __align__(1024) char smem[];
    gemm_body<false, true>(A, B, bias, add, add_ld, C, N, K, K,
                           blockIdx.y * 128, blockIdx.x * 256,
                           blockIdx.x, Wc, plog, smem);
}

// Reduce logits partials (fixed order over 4 column blocks) + bc.
__global__ __launch_bounds__(256) void reduce_logits_kernel(
    const float* __restrict__ plog, const float* __restrict__ bc,
    float* __restrict__ logits)
{
    size_t idx = (size_t)blockIdx.x * 256 + threadIdx.x;   // MTOT*4 total
    float s = bc[idx & 3];
    s += plog[idx];
    s += plog[(size_t)MTOT * 4 + idx];
    s += plog[2 * (size_t)MTOT * 4 + idx];
    s += plog[3 * (size_t)MTOT * 4 + idx];
    logits[idx] = s;
}

// --------------------------- cast kernel -----------------------------------
// Blocks [0, MTOT): stacked X -> Xh.
// Blocks [MTOT, MTOT+5120): straight casts Wq->0, Wkc->1024, Wvc->2048,
//   Woc->4096 (rows of Wh), Wo_s -> Wos16.
// Blocks [MTOT+5120, MTOT+6144): tiled transpose-cast Wv_s -> WvsT16.
__global__ __launch_bounds__(256) void cast_all_kernel(
    const float* __restrict__ X1, const float* __restrict__ X2,
    const float* __restrict__ X3, const float* __restrict__ X4,
    const float* __restrict__ Wq, const float* __restrict__ Wkc,
    const float* __restrict__ Wvc, const float* __restrict__ Woc,
    const float* __restrict__ Wos, const float* __restrict__ Wvs,
    __half* __restrict__ Xh, __half* __restrict__ Wh,
    __half* __restrict__ Wos16, __half* __restrict__ WvsT16)
{
    if (blockIdx.x < MTOT) {
        size_t idx = (size_t)blockIdx.x * 256 + threadIdx.x;
        size_t r = idx >> 8;
        int c4 = (int)(idx & 255) * 4;
        const float* src = (r < NB) ? X1 : (r < 2 * NB) ? X2
                         : (r < 3 * NB) ? X3 : X4;
        float4 v = *(const float4*)&src[(r & (NB - 1)) * DD + c4];
        __half hf[4] = { __float2half(v.x), __float2half(v.y),
                         __float2half(v.z), __float2half(v.w) };
        *(uint2*)&Xh[r * DD + c4] = *(uint2*)hf;
    } else if (blockIdx.x < MTOT + 5120) {
        size_t idx = (size_t)(blockIdx.x - MTOT) * 256 + threadIdx.x;
        int sel = (int)(idx >> 18);             // 2^18 float4 per matrix
        size_t off = (idx & ((1u << 18) - 1)) * 4;
        const float* src = (sel == 0) ? Wq : (sel == 1) ? Wkc
                         : (sel == 2) ? Wvc : (sel == 3) ? Woc : Wos;
        __half* dst = (sel == 4) ? Wos16
                    : Wh + (size_t)((sel == 3) ? 4096 : sel * 1024) * DD;
        float4 v = *(const float4*)&src[off];
        __half h[4] = { __float2half(v.x), __float2half(v.y),
                        __float2half(v.z), __float2half(v.w) };
        *(uint2*)&dst[off] = *(uint2*)h;
    } else {
        __shared__ float tile[32][33];
        const int bb = blockIdx.x - (MTOT + 5120);
        const int i0 = (bb & 31) * 32;         // i tile (cols of Wvs)
        const int m0 = (bb >> 5) * 32;         // m tile (rows of Wvs)
        const int tx = threadIdx.x & 31, ty = threadIdx.x >> 5;   // 32 x 8
        #pragma unroll
        for (int r = 0; r < 4; r++)
            tile[ty * 4 + r][tx] = Wvs[(size_t)(m0 + ty * 4 + r) * DD + i0 + tx];
        __syncthreads();
        const int il = threadIdx.x >> 3;       // 0..31
        const int mq = (threadIdx.x & 7) * 4;  // 0,4,..,28
        __half h[4];
        #pragma unroll
        for (int r = 0; r < 4; r++)
            h[r] = __float2half(tile[mq + r][il]);
        *(uint2*)&WvsT16[(size_t)(i0 + il) * DD + m0 + mq] = *(uint2*)h;
    }
}

// --------------------------- bias kernel -----------------------------------
__device__ __forceinline__ float wsum(float v) {
    #pragma unroll
    for (int o = 16; o; o >>= 1) v += __shfl_xor_sync(0xffffffffu, v, o);
    return v;
}

// Merged: b1a[0..1023]=bq, [1024..3071]=0, [3072+o]=Wos[o,:]@bvs + bos[o].
__global__ __launch_bounds__(256) void bias_all_kernel(
    const float* __restrict__ bq,
    const float* __restrict__ Wos, const float* __restrict__ bvs,
    const float* __restrict__ bos, float* __restrict__ b1a)
{
    int idx = blockIdx.x * 256 + threadIdx.x;   // 128 blocks -> 32768 threads
    if (idx < DD)           b1a[idx] = bq[idx];
    else if (idx < 3 * DD)  b1a[idx] = 0.f;

    int o = blockIdx.x * 8 + (threadIdx.x >> 5);
    int lane = threadIdx.x & 31;
    float s = 0.f;
    for (int k = lane; k < DD; k += 32)
        s = fmaf(Wos[(size_t)o * DD + k], bvs[k], s);
    s = wsum(s);
    if (lane == 0) b1a[3 * DD + o] = s + bos[o];
}

// --------------------------- combine ---------------------------------------
// ctx_i = Vc_i + bv_c - sum_j a_ij Vc_j, fp16 in (C1h) / fp16 out (A2h).
__global__ __launch_bounds__(128) void combine_kernel(
    const __half* __restrict__ C1h,   // Q | Kc | Vc | S  (ld 4096)
    const float* __restrict__ bk, const float* __restrict__ bv,
    __half* __restrict__ A2h)
{
    const int b    = blockIdx.x;
    const int h    = threadIdx.x >> 5;
    const int lane = threadIdx.x & 31;
    const int base_d = h * HD + lane;

    float q[4][8], kc[4][8], vc[4][8];
    #pragma unroll
    for (int i = 0; i < 4; i++) {
        size_t row = (size_t)(i * NB + b) * N1A + base_d;
        #pragma unroll
        for (int e = 0; e < 8; e++) {
            q [i][e] = __half2float(C1h[row + e * 32]);
            kc[i][e] = __half2float(C1h[row + 1024 + e * 32]);
            vc[i][e] = __half2float(C1h[row + 2048 + e * 32]);
        }
    }
    float bke[8], bve[8];
    #pragma unroll
    for (int e = 0; e < 8; e++) {
        bke[e] = bk[base_d + e * 32];
        bve[e] = bv[base_d + e * 32];
    }

    float a[4][4];
    #pragma unroll
    for (int i = 0; i < 4; i++) {
        float s[4];
        #pragma unroll
        for (int j = 0; j < 4; j++) {
            float p = 0.f;
            #pragma unroll
            for (int e = 0; e < 8; e++)
                p = fmaf(q[i][e], kc[i][e] - kc[j][e] + bke[e], p);
            s[j] = wsum(p) * (1.f / 16.f);
        }
        float m = -1e30f;
        #pragma unroll
        for (int j = 0; j < 4; j++) if (j != i && s[j] > m) m = s[j];
        float den = 0.f;
        #pragma unroll
        for (int j = 0; j < 4; j++) {
            float ex = (j == i) ? 0.f : __expf(s[j] - m);
            a[i][j] = ex; den += ex;
        }
        float inv = 1.f / den;
        #pragma unroll
        for (int j = 0; j < 4; j++) a[i][j] *= inv;
    }

    #pragma unroll
    for (int i = 0; i < 4; i++) {
        __half* row = A2h + (size_t)(i * NB + b) * DD;
        #pragma unroll
        for (int e = 0; e < 8; e++) {
            float c = vc[i][e] + bve[e];
            #pragma unroll
            for (int j = 0; j < 4; j++)
                c = fmaf(-a[i][j], vc[j][e], c);
            row[base_d + e * 32] = __float2half(c);
        }
    }
}

// ---------------------------------------------------------------------------
extern "C" void kernel_launch(void* const* d_in, const int* in_sizes, int n_in,
                              void* d_out, int out_size)
{
    const float* X1   = (const float*)d_in[0];
    const float* X2   = (const float*)d_in[1];
    const float* X3   = (const float*)d_in[2];
    const float* X4   = (const float*)d_in[3];
    const float* Wq   = (const float*)d_in[4];
    const float* bq   = (const float*)d_in[5];
    const float* Wv_s = (const float*)d_in[8];
    const float* bv_s = (const float*)d_in[9];
    const float* Wo_s = (const float*)d_in[10];
    const float* bo_s = (const float*)d_in[11];
    const float* Wk_c = (const float*)d_in[12];
    const float* bk_c = (const float*)d_in[13];
    const float* Wv_c = (const float*)d_in[14];
    const float* bv_c = (const float*)d_in[15];
    const float* Wo_c = (const float*)d_in[16];
    const float* bo_c = (const float*)d_in[17];
    const float* Wc   = (const float*)d_in[18];
    const float* bc   = (const float*)d_in[19];

    float* out    = (float*)d_out;
    float* logits = out + (size_t)MTOT * DD;

    __half *gXh, *gWh, *gC1h, *gA2h, *gWos16, *gWvsT16;
    float *gPlog, *gb1a, *gzero;
    cudaGetSymbolAddress((void**)&gXh,     g_Xh);
    cudaGetSymbolAddress((void**)&gWh,     g_Wh);
    cudaGetSymbolAddress((void**)&gC1h,    g_C1h);
    cudaGetSymbolAddress((void**)&gA2h,    g_A2h);
    cudaGetSymbolAddress((void**)&gWos16,  g_Wos16);
    cudaGetSymbolAddress((void**)&gWvsT16, g_WvsT16);
    cudaGetSymbolAddress((void**)&gPlog,   g_plog);
    cudaGetSymbolAddress((void**)&gb1a,    g_b1a);
    cudaGetSymbolAddress((void**)&gzero,   g_zero);

    cudaFuncSetAttribute((const void*)gemm1_kernel,
                         cudaFuncAttributeMaxDynamicSharedMemorySize, GEMM_SMEM);
    cudaFuncSetAttribute((const void*)gemm2_kernel,
                         cudaFuncAttributeMaxDynamicSharedMemorySize, GEMM_SMEM);

    // prep: all fp16 casts (X, 5 weight matrices, Wv_s^T) in one launch
    cast_all_kernel<<<MTOT + 6144, 256>>>(
        X1, X2, X3, X4, Wq, Wk_c, Wv_c, Wo_c, Wo_s, Wv_s,
        gXh, gWh, gWos16, gWvsT16);

    // Weff = Wo_s@Wv_s (fp16 in, fp32 accum, fp16 out straight into Wh S block)
    gemm1_kernel<<<dim3(4, 8), 256, GEMM_SMEM>>>(
        (const uint16_t*)gWos16, (const uint16_t*)gWvsT16, gzero,
        gWh + (size_t)3072 * DD, DD, DD);

    bias_all_kernel<<<128, 256>>>(bq, Wo_s, bv_s, bo_s, gb1a);

    // GEMM1 (fp16 in/out): C1h[32768,4096] = Xh @ [Wq;Wkc;Wvc;Weff]^T + b1a
    gemm1_kernel<<<dim3(N1A / 256, MTOT / 128), 256, GEMM_SMEM>>>(
        (const uint16_t*)gXh, (const uint16_t*)gWh, gb1a, gC1h, N1A, DD);

    // attention combine -> ctx fp16 into A2h
    combine_kernel<<<NB, 128>>>(gC1h, bk_c, bv_c, gA2h);

    // GEMM2 (fp16 in, fp32 out): d = ctx @ Wo_c^T + bo_c + S, with fused
    // per-column-block logits partials (deterministic).
    gemm2_kernel<<<dim3(DD / 256, MTOT / 128), 256, GEMM_SMEM>>>(
        (const uint16_t*)gA2h, (const uint16_t*)(gWh + (size_t)4096 * DD),
        bo_c, gC1h + 3072, N1A, out, DD, DD, Wc, gPlog);

    // logits = sum of 4 column-block partials (fixed order) + bc
    reduce_logits_kernel<<<MTOT * 4 / 256, 256>>>(gPlog, bc, logits);
}